// round 2
// baseline (speedup 1.0000x reference)
#include <cuda_runtime.h>
#include <math.h>

#define B_  32
#define D_  256
#define K_  1024
#define HW_ 1024          // 32*32
#define N_  32768         // B_*HW_
#define Q_ELEMS 8388608   // B_*D_*HW_
#define ENC_OFF 8388610   // quantized + loss + perplexity
#define ENC_ELEMS 33554432

// -------- scratch (device globals; no allocation allowed) --------
__device__ float g_ct[D_ * K_];     // codebook transposed [d][k]
__device__ float g_cnorm[K_];
__device__ float g_znorm[N_];
__device__ int   g_idx[N_];
__device__ int   g_counts[K_];
__device__ float g_part[8192];

// -------- codebook transpose: cb[k][d] -> g_ct[d][k] --------
__global__ void transpose_cb_kernel(const float* __restrict__ cb) {
    __shared__ float tile[32][33];
    int tx = threadIdx.x, ty = threadIdx.y;
    int kb = blockIdx.x * 32, db = blockIdx.y * 32;
    #pragma unroll
    for (int i = 0; i < 4; i++)
        tile[ty + i * 8][tx] = cb[(size_t)(kb + ty + i * 8) * D_ + db + tx];
    __syncthreads();
    #pragma unroll
    for (int i = 0; i < 4; i++)
        g_ct[(size_t)(db + ty + i * 8) * K_ + kb + tx] = tile[tx][ty + i * 8];
}

// -------- cnorm + zero counts (128 blocks x 8 warps = 1024 codes) --------
__global__ void cnorm_kernel(const float* __restrict__ cb) {
    int tid = threadIdx.x;
    int gtid = blockIdx.x * 256 + tid;
    if (gtid < K_) g_counts[gtid] = 0;
    int wid = tid >> 5, lane = tid & 31;
    int code = blockIdx.x * 8 + wid;
    float s = 0.f;
    #pragma unroll
    for (int j = 0; j < 8; j++) {
        float v = cb[(size_t)code * D_ + lane + 32 * j];
        s = fmaf(v, v, s);
    }
    #pragma unroll
    for (int o = 16; o > 0; o >>= 1)
        s += __shfl_down_sync(0xffffffffu, s, o);
    if (lane == 0) g_cnorm[code] = s;
}

// -------- znorm per flattened row (coalesced over hw) --------
__global__ void znorm_kernel(const float* __restrict__ z_e) {
    int r = blockIdx.x * 256 + threadIdx.x;   // row n = b*1024 + h*32 + w
    int b = r >> 10, hw = r & 1023;
    const float* p = z_e + (size_t)b * (D_ * HW_) + hw;
    float s = 0.f;
    #pragma unroll 8
    for (int d = 0; d < D_; d++) {
        float v = p[(size_t)d * HW_];
        s = fmaf(v, v, s);
    }
    g_znorm[r] = s;
}

// -------- argmin over codes: tiled fp32 GEMM + running min --------
// Block: 256 threads, TM=64 rows, TK=64 codes, D chunk 32; thread micro-tile 4x4.
__global__ __launch_bounds__(256) void argmin_kernel(const float* __restrict__ z_e) {
    __shared__ float zs[32][64];
    __shared__ float cs[32][64];
    int tid = threadIdx.x;
    int tx = tid & 15, ty = tid >> 4;
    int R0 = blockIdx.x * 64;           // 64 consecutive rows (never cross b: 64|1024)
    int b = R0 >> 10, hw = R0 & 1023;
    const float* zbase = z_e + (size_t)b * (D_ * HW_) + hw;

    float zn[4];
    #pragma unroll
    for (int j = 0; j < 4; j++) zn[j] = g_znorm[R0 + ty * 4 + j];

    float bestv[4];
    int   bestk[4];
    #pragma unroll
    for (int j = 0; j < 4; j++) { bestv[j] = 3.402823466e38f; bestk[j] = 0; }

    for (int k0 = 0; k0 < K_; k0 += 64) {
        float acc[4][4];
        #pragma unroll
        for (int j = 0; j < 4; j++)
            #pragma unroll
            for (int q = 0; q < 4; q++) acc[j][q] = 0.f;

        for (int d0 = 0; d0 < D_; d0 += 32) {
            __syncthreads();
            #pragma unroll
            for (int i = 0; i < 8; i++) {
                int e = (i << 8) + tid;
                int dd = e >> 6, r = e & 63;
                zs[dd][r] = zbase[(size_t)(d0 + dd) * HW_ + r];
                cs[dd][r] = g_ct[(size_t)(d0 + dd) * K_ + k0 + r];
            }
            __syncthreads();
            #pragma unroll
            for (int d = 0; d < 32; d++) {
                float4 zv = *reinterpret_cast<const float4*>(&zs[d][ty << 2]);
                float4 cv = *reinterpret_cast<const float4*>(&cs[d][tx << 2]);
                acc[0][0] = fmaf(zv.x, cv.x, acc[0][0]);
                acc[0][1] = fmaf(zv.x, cv.y, acc[0][1]);
                acc[0][2] = fmaf(zv.x, cv.z, acc[0][2]);
                acc[0][3] = fmaf(zv.x, cv.w, acc[0][3]);
                acc[1][0] = fmaf(zv.y, cv.x, acc[1][0]);
                acc[1][1] = fmaf(zv.y, cv.y, acc[1][1]);
                acc[1][2] = fmaf(zv.y, cv.z, acc[1][2]);
                acc[1][3] = fmaf(zv.y, cv.w, acc[1][3]);
                acc[2][0] = fmaf(zv.z, cv.x, acc[2][0]);
                acc[2][1] = fmaf(zv.z, cv.y, acc[2][1]);
                acc[2][2] = fmaf(zv.z, cv.z, acc[2][2]);
                acc[2][3] = fmaf(zv.z, cv.w, acc[2][3]);
                acc[3][0] = fmaf(zv.w, cv.x, acc[3][0]);
                acc[3][1] = fmaf(zv.w, cv.y, acc[3][1]);
                acc[3][2] = fmaf(zv.w, cv.z, acc[3][2]);
                acc[3][3] = fmaf(zv.w, cv.w, acc[3][3]);
            }
        }

        // scores (replicate reference rounding: fl(fl(zn+cn) - fl(2*dot))) + min reduce
        #pragma unroll
        for (int j = 0; j < 4; j++) {
            float v = 3.402823466e38f; int kk = 0;
            #pragma unroll
            for (int q = 0; q < 4; q++) {
                int kidx = k0 + tx * 4 + q;
                float A  = zn[j] + g_cnorm[kidx];   // fp32 round
                float Dv = A - 2.0f * acc[j][q];    // 2*dot exact, subtract rounds
                if (Dv < v) { v = Dv; kk = kidx; }  // ascending q keeps lowest idx on tie
            }
            // reduce over 16 tx lanes (lane bits 0..3), lowest-index tie-break
            #pragma unroll
            for (int o = 8; o > 0; o >>= 1) {
                float ov = __shfl_xor_sync(0xffffffffu, v, o);
                int   ok = __shfl_xor_sync(0xffffffffu, kk, o);
                if (ov < v || (ov == v && ok < kk)) { v = ov; kk = ok; }
            }
            if (v < bestv[j] || (v == bestv[j] && kk < bestk[j])) {
                bestv[j] = v; bestk[j] = kk;
            }
        }
    }
    if (tx == 0) {
        #pragma unroll
        for (int j = 0; j < 4; j++)
            g_idx[R0 + ty * 4 + j] = bestk[j];
    }
}

// -------- gather quantized (NCHW) + per-block SSE partials --------
__global__ void output_kernel(const float* __restrict__ z_e,
                              const float* __restrict__ cb,
                              float* __restrict__ out) {
    __shared__ float red[256];
    int tid = threadIdx.x;
    size_t e = ((size_t)blockIdx.x * 256 + tid) * 4;  // NCHW element index
    int w = (int)(e & 31);
    int h = (int)((e >> 5) & 31);
    int d = (int)((e >> 10) & 255);
    int b = (int)(e >> 18);
    int n = b * 1024 + h * 32 + w;
    float4 z = *reinterpret_cast<const float4*>(z_e + e);
    float q0 = cb[(size_t)g_idx[n + 0] * D_ + d];
    float q1 = cb[(size_t)g_idx[n + 1] * D_ + d];
    float q2 = cb[(size_t)g_idx[n + 2] * D_ + d];
    float q3 = cb[(size_t)g_idx[n + 3] * D_ + d];
    *reinterpret_cast<float4*>(out + e) = make_float4(q0, q1, q2, q3);
    float d0 = q0 - z.x, d1 = q1 - z.y, d2 = q2 - z.z, d3 = q3 - z.w;
    red[tid] = d0 * d0 + d1 * d1 + d2 * d2 + d3 * d3;
    __syncthreads();
    for (int o = 128; o > 0; o >>= 1) {
        if (tid < o) red[tid] += red[tid + o];
        __syncthreads();
    }
    if (tid == 0) g_part[blockIdx.x] = red[0];
}

// -------- zero-fill encodings (float2: base offset is 8B-aligned) --------
__global__ void zero_enc_kernel(float* __restrict__ out) {
    float2* enc = reinterpret_cast<float2*>(out + ENC_OFF);
    size_t t = (size_t)blockIdx.x * 256 + threadIdx.x;
    #pragma unroll
    for (int i = 0; i < 8; i++)
        enc[t + (size_t)i * 2097152] = make_float2(0.f, 0.f);
}

// -------- scatter one-hot + integer counts --------
__global__ void scatter_kernel(float* __restrict__ out) {
    int n = blockIdx.x * 256 + threadIdx.x;
    int idx = g_idx[n];
    atomicAdd(&g_counts[idx], 1);
    out[ENC_OFF + (size_t)n * K_ + idx] = 1.0f;
}

// -------- deterministic finalize: loss + perplexity --------
__global__ void finalize_kernel(float* __restrict__ out) {
    __shared__ float red[1024];
    int t = threadIdx.x;
    float s = 0.f;
    #pragma unroll
    for (int i = 0; i < 8; i++) s += g_part[t + i * 1024];
    red[t] = s;
    __syncthreads();
    for (int o = 512; o > 0; o >>= 1) {
        if (t < o) red[t] += red[t + o];
        __syncthreads();
    }
    float sse = red[0];
    __syncthreads();
    float p = (float)g_counts[t] * (1.0f / 32768.0f);
    red[t] = p * logf(p + 1e-10f);
    __syncthreads();
    for (int o = 512; o > 0; o >>= 1) {
        if (t < o) red[t] += red[t + o];
        __syncthreads();
    }
    if (t == 0) {
        float mse = sse * (1.0f / 8388608.0f);
        out[Q_ELEMS]     = 1.25f * mse;        // q_latent + BETA*e_latent = 1.25*mse
        out[Q_ELEMS + 1] = expf(-red[0]);      // perplexity
    }
}

extern "C" void kernel_launch(void* const* d_in, const int* in_sizes, int n_in,
                              void* d_out, int out_size) {
    // z_e is the big input, codebook the small one (defensive order check)
    const float* z_e = (const float*)d_in[0];
    const float* cb  = (const float*)d_in[1];
    if (n_in >= 2 && in_sizes[0] < in_sizes[1]) {
        z_e = (const float*)d_in[1];
        cb  = (const float*)d_in[0];
    }
    float* out = (float*)d_out;

    transpose_cb_kernel<<<dim3(32, 8), dim3(32, 8)>>>(cb);
    cnorm_kernel<<<128, 256>>>(cb);
    znorm_kernel<<<128, 256>>>(z_e);
    argmin_kernel<<<512, 256>>>(z_e);
    output_kernel<<<8192, 256>>>(z_e, cb, out);
    zero_enc_kernel<<<8192, 256>>>(out);
    scatter_kernel<<<128, 256>>>(out);
    finalize_kernel<<<1, 1024>>>(out);
}